// round 15
// baseline (speedup 1.0000x reference)
#include <cuda_runtime.h>
#include <cuda_fp16.h>
#include <stdint.h>
#include <math.h>

#define BZ   2
#define TT   2048
#define DD   1024
#define HH   16
#define DKK  64
#define DFF  4096
#define MM   (BZ*TT)          // 4096 rows total

// ----------------------------------------------------------------------------
// Scratch (device globals — no runtime allocation allowed)
// ----------------------------------------------------------------------------
__device__ __half g_h16 [MM*DD];                // LN output (fp16 GEMM A operand)
__device__ __half g_q16 [MM*DD];
__device__ __half g_k16 [MM*DD];
__device__ __half g_v16 [MM*DD];
__device__ __half g_ctx16[MM*DD];               // attention output (fp16)
__device__ float  g_x2  [MM*DD];                // x + attn (fp32 residual stream)
__device__ __half g_act16[(size_t)MM*DFF];      // GELU(fc1) activations (fp16)
// fp16 weight copies
__device__ __half g_wq16 [DD*DD];
__device__ __half g_wk16 [DD*DD];
__device__ __half g_wv16 [DD*DD];
__device__ __half g_wo16 [DD*DD];
__device__ __half g_wfc1_16[(size_t)DD*DFF];
__device__ __half g_wfc2_16[(size_t)DFF*DD];

// ----------------------------------------------------------------------------
// Baseline-PTX tensor-core helpers (sm_80-level: valid on compute_103)
// ----------------------------------------------------------------------------
__device__ __forceinline__ uint32_t smem_u32(const void* p) {
    uint32_t a;
    asm("{ .reg .u64 t; cvta.to.shared.u64 t, %1; cvt.u32.u64 %0, t; }" : "=r"(a) : "l"(p));
    return a;
}
__device__ __forceinline__ void ldsm_x4(uint32_t r[4], uint32_t a) {
    asm volatile("ldmatrix.sync.aligned.m8n8.x4.shared.b16 {%0,%1,%2,%3}, [%4];"
        : "=r"(r[0]), "=r"(r[1]), "=r"(r[2]), "=r"(r[3]) : "r"(a));
}
__device__ __forceinline__ void ldsm_x4_t(uint32_t r[4], uint32_t a) {
    asm volatile("ldmatrix.sync.aligned.m8n8.x4.trans.shared.b16 {%0,%1,%2,%3}, [%4];"
        : "=r"(r[0]), "=r"(r[1]), "=r"(r[2]), "=r"(r[3]) : "r"(a));
}
__device__ __forceinline__ void mma16816(float c[4], const uint32_t a[4], const uint32_t b[2]) {
    asm volatile("mma.sync.aligned.m16n8k16.row.col.f32.f16.f16.f32 "
        "{%0,%1,%2,%3}, {%4,%5,%6,%7}, {%8,%9}, {%0,%1,%2,%3};"
        : "+f"(c[0]), "+f"(c[1]), "+f"(c[2]), "+f"(c[3])
        : "r"(a[0]), "r"(a[1]), "r"(a[2]), "r"(a[3]), "r"(b[0]), "r"(b[1]));
}
#define CP_ASYNC16(dst, src) \
    asm volatile("cp.async.cg.shared.global [%0], [%1], 16;" :: "r"(dst), "l"(src))
#define CP_COMMIT() asm volatile("cp.async.commit_group;")
#define CP_WAIT1()  asm volatile("cp.async.wait_group 1;")
#define CP_WAIT0()  asm volatile("cp.async.wait_group 0;")

__device__ __forceinline__ uint32_t pack_h2(float a, float b) {
    __half2 h = __floats2half2_rn(a, b);
    return *reinterpret_cast<uint32_t*>(&h);
}

// ----------------------------------------------------------------------------
// Fused fp32 -> fp16 conversion of ALL six weight tensors in one launch.
// ----------------------------------------------------------------------------
__global__ void __launch_bounds__(256) cvt16_all_kernel(
        const float* __restrict__ s0, const float* __restrict__ s1,
        const float* __restrict__ s2, const float* __restrict__ s3,
        const float* __restrict__ s4, const float* __restrict__ s5,
        __half* __restrict__ d0, __half* __restrict__ d1,
        __half* __restrict__ d2, __half* __restrict__ d3,
        __half* __restrict__ d4, __half* __restrict__ d5)
{
    const float* s; __half* d; int n;
    switch (blockIdx.y) {
        case 0:  s = s0; d = d0; n = DD*DD;  break;
        case 1:  s = s1; d = d1; n = DD*DD;  break;
        case 2:  s = s2; d = d2; n = DD*DD;  break;
        case 3:  s = s3; d = d3; n = DD*DD;  break;
        case 4:  s = s4; d = d4; n = DD*DFF; break;
        default: s = s5; d = d5; n = DFF*DD; break;
    }
    int i = (blockIdx.x * 256 + threadIdx.x) * 4;
    if (i < n) {
        float4 v = *reinterpret_cast<const float4*>(s + i);
        __align__(8) __half2 hv[2] = { __floats2half2_rn(v.x, v.y),
                                       __floats2half2_rn(v.z, v.w) };
        *reinterpret_cast<uint2*>(d + i) = *reinterpret_cast<uint2*>(hv);
    }
}

// ----------------------------------------------------------------------------
// LayerNorm (torch semantics: unbiased std ddof=1, eps added to std). fp16 out.
// Warp-per-row, 8 rows per 256-thread block, NO __syncthreads.
// ----------------------------------------------------------------------------
__global__ void __launch_bounds__(256) ln_kernel(const float* __restrict__ x,
        const float* __restrict__ g, const float* __restrict__ b,
        __half* __restrict__ out)
{
    int row  = blockIdx.x * 8 + (threadIdx.x >> 5);
    int lane = threadIdx.x & 31;
    const float* xr = x + (size_t)row * DD;

    float4 xv[8];
    float s1 = 0.f, s2 = 0.f;
    #pragma unroll
    for (int i = 0; i < 8; i++) {
        xv[i] = *reinterpret_cast<const float4*>(xr + i*128 + lane*4);
        s1 += xv[i].x + xv[i].y + xv[i].z + xv[i].w;
        s2 += xv[i].x*xv[i].x + xv[i].y*xv[i].y + xv[i].z*xv[i].z + xv[i].w*xv[i].w;
    }
    #pragma unroll
    for (int o = 16; o > 0; o >>= 1) {
        s1 += __shfl_xor_sync(0xffffffffu, s1, o);
        s2 += __shfl_xor_sync(0xffffffffu, s2, o);
    }
    float mean = s1 * (1.0f / DD);
    float var  = (s2 - s1 * mean) * (1.0f / (DD - 1));   // unbiased (ddof=1)
    var = fmaxf(var, 0.f);
    float rstd = 1.0f / (sqrtf(var) + 1e-6f);            // eps added to std

    __half* orow = out + (size_t)row * DD;
    #pragma unroll
    for (int i = 0; i < 8; i++) {
        float4 gv = *reinterpret_cast<const float4*>(g + i*128 + lane*4);
        float4 bv = *reinterpret_cast<const float4*>(b + i*128 + lane*4);
        float o0 = (xv[i].x - mean) * gv.x * rstd + bv.x;
        float o1 = (xv[i].y - mean) * gv.y * rstd + bv.y;
        float o2 = (xv[i].z - mean) * gv.z * rstd + bv.z;
        float o3 = (xv[i].w - mean) * gv.w * rstd + bv.w;
        __align__(8) __half2 hv[2] = { __floats2half2_rn(o0, o1),
                                       __floats2half2_rn(o2, o3) };
        *reinterpret_cast<uint2*>(orow + i*128 + lane*4) = *reinterpret_cast<uint2*>(hv);
    }
}

// ----------------------------------------------------------------------------
// mma.sync fp16 GEMM: C = A @ B (+bias/GELU/resid). CTA 128x128, BK=32,
// 4 warps x 64x64 warp tiles, 3-stage cp.async pipeline, one __syncthreads per
// K-step. R15 scheduling: next-stage cp.async issued BEFORE the MMA block, and
// both ks sub-steps' ldmatrix batched ahead of all 64 MMAs.
// ----------------------------------------------------------------------------
#define ASTR 40
#define BSTR 136
#define A_STG (128*ASTR)              // halves per A stage
#define B_STG (32*BSTR)               // halves per B stage
#define GEMM_SMEM ((3*A_STG + 3*B_STG)*2)   // 56832 bytes

template<bool GELU, bool RESID, bool BIAS, bool OUT16, int NB>
__global__ void __launch_bounds__(128) gemm_mma_kernel(
        const __half* __restrict__ A,
        const __half* __restrict__ B0, const __half* __restrict__ B1,
        const __half* __restrict__ B2,
        const float* __restrict__ bias, const float* __restrict__ resid,
        void* C0, void* C1, void* C2, int Kdim, int Ndim)
{
    extern __shared__ __align__(16) char gsm[];
    __half* As = reinterpret_cast<__half*>(gsm);
    __half* Bs = As + 3*A_STG;

    int tid = threadIdx.x;
    int wid = tid >> 5, lane = tid & 31;
    int wm = wid & 1, wn = wid >> 1;    // 2x2 warps, each 64x64

    const __half* B = B0;
    void* Cv = C0;
    if (NB == 3) {
        if (blockIdx.z == 1)      { B = B1; Cv = C1; }
        else if (blockIdx.z == 2) { B = B2; Cv = C2; }
    }

    int brow = blockIdx.y * 128;
    int bcol = blockIdx.x * 128;
    const __half* Ag = A + (size_t)brow * Kdim;
    const __half* Bg = B + bcol;

    float acc[4][8][4];
    #pragma unroll
    for (int mt = 0; mt < 4; mt++)
        #pragma unroll
        for (int nt = 0; nt < 8; nt++)
            #pragma unroll
            for (int e = 0; e < 4; e++) acc[mt][nt][e] = 0.f;

    auto load_tiles = [&](int stg, int k0) {
        uint32_t ab = smem_u32(As + stg * A_STG);
        #pragma unroll
        for (int u = 0; u < 4; u++) {
            int c = tid + u * 128;
            int row = c >> 2, seg = c & 3;
            CP_ASYNC16(ab + (row*ASTR + seg*8)*2,
                       Ag + (size_t)row * Kdim + k0 + seg*8);
        }
        uint32_t bb = smem_u32(Bs + stg * B_STG);
        #pragma unroll
        for (int u = 0; u < 4; u++) {
            int c = tid + u * 128;
            int row = c >> 4, seg = c & 15;
            CP_ASYNC16(bb + (row*BSTR + seg*8)*2,
                       Bg + (size_t)(k0 + row) * Ndim + seg*8);
        }
    };

    int nk = Kdim >> 5;
    load_tiles(0, 0);  CP_COMMIT();
    load_tiles(1, 32); CP_COMMIT();    // nk >= 2 always (K >= 64)

    int lrow = lane & 15, lcol = lane >> 4;
    int stg = 0;

    for (int i = 0; i < nk; i++) {
        if (i == nk - 1) { CP_WAIT0(); } else { CP_WAIT1(); }
        __syncthreads();     // stage i visible; compute i-1 done everywhere

        // Issue next-stage global loads FIRST so their latency overlaps the
        // MMA block below. Target slot (i+2)%3 == (i-1)%3: compute finished
        // before this barrier.
        if (i + 2 < nk) {
            int ns = stg + 2; if (ns >= 3) ns -= 3;
            load_tiles(ns, (i + 2) << 5);
            CP_COMMIT();
        }

        uint32_t ab = smem_u32(As + stg * A_STG);
        uint32_t bb = smem_u32(Bs + stg * B_STG);

        // Batch BOTH ks sub-steps' fragments, then run all 64 MMAs: the
        // ks=1 ldmatrix latency hides under the ks=0 MMA stream.
        uint32_t af[2][4][4], bf[2][4][4];
        #pragma unroll
        for (int ks = 0; ks < 2; ks++) {
            #pragma unroll
            for (int mt = 0; mt < 4; mt++)
                ldsm_x4(af[ks][mt], ab + ((wm*64 + mt*16 + lrow)*ASTR + ks*16 + lcol*8)*2);
            #pragma unroll
            for (int t = 0; t < 4; t++)
                ldsm_x4_t(bf[ks][t], bb + ((ks*16 + lrow)*BSTR + wn*64 + t*16 + lcol*8)*2);
        }
        #pragma unroll
        for (int ks = 0; ks < 2; ks++)
            #pragma unroll
            for (int mt = 0; mt < 4; mt++)
                #pragma unroll
                for (int nt = 0; nt < 8; nt++)
                    mma16816(acc[mt][nt], af[ks][mt], &bf[ks][nt >> 1][(nt & 1) * 2]);

        if (++stg == 3) stg = 0;
    }

    int r0 = brow + wm*64 + (lane >> 2);
    int c0 = bcol + wn*64 + (lane & 3) * 2;
    #pragma unroll
    for (int mt = 0; mt < 4; mt++) {
        #pragma unroll
        for (int hh = 0; hh < 2; hh++) {
            int r = r0 + mt*16 + hh*8;
            #pragma unroll
            for (int nt = 0; nt < 8; nt++) {
                int c = c0 + nt*8;
                float v0 = acc[mt][nt][hh*2 + 0];
                float v1 = acc[mt][nt][hh*2 + 1];
                if (BIAS) { v0 += bias[c]; v1 += bias[c + 1]; }
                if (GELU) {
                    v0 = 0.5f * v0 * (1.0f + erff(v0 * 0.70710678118f));
                    v1 = 0.5f * v1 * (1.0f + erff(v1 * 0.70710678118f));
                }
                if (RESID) {
                    v0 += resid[(size_t)r * Ndim + c];
                    v1 += resid[(size_t)r * Ndim + c + 1];
                }
                if (OUT16) {
                    __half2 hv = __floats2half2_rn(v0, v1);
                    *reinterpret_cast<__half2*>((__half*)Cv + (size_t)r * Ndim + c) = hv;
                } else {
                    *reinterpret_cast<float2*>((float*)Cv + (size_t)r * Ndim + c) =
                        make_float2(v0, v1);
                }
            }
        }
    }
}

// ----------------------------------------------------------------------------
// FA2-style causal attention via mma.sync, 128-query blocks, 8 warps,
// cp.async double-buffered K/V (64-key tiles). q/k/v fp16 [b,t,h*64+d].
// Grid (HH, TT/128, BZ) with REVERSED qb so heavy causal blocks launch first.
// ----------------------------------------------------------------------------
#define QSTR 72
#define ATTN_SMEM (128*QSTR*2 + 4*64*QSTR*2)   // Q + 2x(K,V) = 55296 B

__global__ void __launch_bounds__(256, 2) attn_mma_kernel(
        const __half* __restrict__ q, const __half* __restrict__ k,
        const __half* __restrict__ v, __half* __restrict__ ctx)
{
    extern __shared__ __align__(16) char dsm[];
    __half* Qs = reinterpret_cast<__half*>(dsm);
    __half* Kb[2] = { Qs + 128*QSTR,             Qs + 128*QSTR + 64*QSTR };
    __half* Vb[2] = { Qs + 128*QSTR + 2*64*QSTR, Qs + 128*QSTR + 3*64*QSTR };

    int head = blockIdx.x;
    int qb   = gridDim.y - 1 - blockIdx.y;   // heavy blocks (large qb) first
    int b    = blockIdx.z;
    int tid = threadIdx.x, wid = tid >> 5, lane = tid & 31;
    const int ldg = HH * DKK;   // 1024

    const __half* qbase = q + (size_t)(b*TT + qb*128) * ldg + head*DKK;
    const __half* kbase = k + (size_t)(b*TT) * ldg + head*DKK;
    const __half* vbase = v + (size_t)(b*TT) * ldg + head*DKK;

    #pragma unroll
    for (int u = 0; u < 4; u++) {
        int c = tid + u * 256;
        int row = c >> 3, seg = c & 7;
        *reinterpret_cast<uint4*>(&Qs[row*QSTR + seg*8]) =
            *reinterpret_cast<const uint4*>(qbase + (size_t)row * ldg + seg*8);
    }

    auto load_kv = [&](int buf, int kb) {
        uint32_t kB = smem_u32(Kb[buf]);
        uint32_t vB = smem_u32(Vb[buf]);
        #pragma unroll
        for (int u = 0; u < 2; u++) {
            int c = tid + u * 256;
            int row = c >> 3, seg = c & 7;
            const __half* ks = kbase + (size_t)(kb*64 + row) * ldg + seg*8;
            const __half* vs = vbase + (size_t)(kb*64 + row) * ldg + seg*8;
            CP_ASYNC16(kB + (row*QSTR + seg*8)*2, ks);
            CP_ASYNC16(vB + (row*QSTR + seg*8)*2, vs);
        }
    };

    int nkb = 2*qb + 2;            // key tiles 0 .. 2qb+1
    load_kv(0, 0);
    CP_COMMIT();
    __syncthreads();               // Q visible

    uint32_t qsb = smem_u32(Qs);
    int lrow = lane & 15, lcol = lane >> 4;
    uint32_t qf[4][4];
    #pragma unroll
    for (int kt = 0; kt < 4; kt++)
        ldsm_x4(qf[kt], qsb + ((wid*16 + lrow)*QSTR + kt*16 + lcol*8)*2);

    float m_i[2] = {-1e30f, -1e30f}, l_i[2] = {0.f, 0.f};
    float oacc[8][4];
    #pragma unroll
    for (int nt = 0; nt < 8; nt++)
        #pragma unroll
        for (int e = 0; e < 4; e++) oacc[nt][e] = 0.f;

    int wr_lo = qb*128 + wid*16;
    int qrow0 = wr_lo + (lane >> 2);

    for (int kb = 0; kb < nkb; kb++) {
        int buf = kb & 1;
        CP_WAIT0();
        __syncthreads();
        if (kb + 1 < nkb) { load_kv(buf ^ 1, kb + 1); CP_COMMIT(); }

        if (kb*64 <= wr_lo + 15) {
            uint32_t ksb = smem_u32(Kb[buf]);
            uint32_t vsb = smem_u32(Vb[buf]);
            bool need_mask = (kb*64 + 63 > wr_lo);

            float sacc[8][4];
            #pragma unroll
            for (int nt = 0; nt < 8; nt++)
                #pragma unroll
                for (int e = 0; e < 4; e++) sacc[nt][e] = 0.f;

            #pragma unroll
            for (int kt = 0; kt < 4; kt++) {
                #pragma unroll
                for (int np = 0; np < 4; np++) {
                    uint32_t bf[4];
                    int nrow = np*16 + (lane & 7) + ((lane >= 16) ? 8 : 0);
                    int koff = kt*16 + ((lane & 8) ? 8 : 0);
                    ldsm_x4(bf, ksb + (nrow*QSTR + koff)*2);
                    mma16816(sacc[np*2],     qf[kt], &bf[0]);
                    mma16816(sacc[np*2 + 1], qf[kt], &bf[2]);
                }
            }

            if (need_mask) {
                #pragma unroll
                for (int nt = 0; nt < 8; nt++) {
                    int kcol = kb*64 + nt*8 + (lane & 3)*2;
                    #pragma unroll
                    for (int e = 0; e < 4; e++) {
                        int r = qrow0 + ((e >= 2) ? 8 : 0);
                        int c = kcol + (e & 1);
                        sacc[nt][e] = (c <= r) ? sacc[nt][e] * 0.125f : -1e30f;
                    }
                }
            } else {
                #pragma unroll
                for (int nt = 0; nt < 8; nt++)
                    #pragma unroll
                    for (int e = 0; e < 4; e++) sacc[nt][e] *= 0.125f;
            }

            float mx[2] = {-1e30f, -1e30f};
            #pragma unroll
            for (int nt = 0; nt < 8; nt++) {
                mx[0] = fmaxf(mx[0], fmaxf(sacc[nt][0], sacc[nt][1]));
                mx[1] = fmaxf(mx[1], fmaxf(sacc[nt][2], sacc[nt][3]));
            }
            #pragma unroll
            for (int hh = 0; hh < 2; hh++) {
                mx[hh] = fmaxf(mx[hh], __shfl_xor_sync(0xffffffffu, mx[hh], 1));
                mx[hh] = fmaxf(mx[hh], __shfl_xor_sync(0xffffffffu, mx[hh], 2));
            }
            float mnew[2] = { fmaxf(m_i[0], mx[0]), fmaxf(m_i[1], mx[1]) };
            float corr[2] = { __expf(m_i[0] - mnew[0]), __expf(m_i[1] - mnew[1]) };
            float ps[2] = {0.f, 0.f};
            #pragma unroll
            for (int nt = 0; nt < 8; nt++) {
                #pragma unroll
                for (int e = 0; e < 4; e++) {
                    float p = __expf(sacc[nt][e] - mnew[(e >= 2) ? 1 : 0]);
                    sacc[nt][e] = p;
                    ps[(e >= 2) ? 1 : 0] += p;
                }
            }
            #pragma unroll
            for (int hh = 0; hh < 2; hh++) {
                ps[hh] += __shfl_xor_sync(0xffffffffu, ps[hh], 1);
                ps[hh] += __shfl_xor_sync(0xffffffffu, ps[hh], 2);
                l_i[hh] = l_i[hh] * corr[hh] + ps[hh];
                m_i[hh] = mnew[hh];
            }
            #pragma unroll
            for (int nt = 0; nt < 8; nt++) {
                oacc[nt][0] *= corr[0]; oacc[nt][1] *= corr[0];
                oacc[nt][2] *= corr[1]; oacc[nt][3] *= corr[1];
            }

            #pragma unroll
            for (int kt = 0; kt < 4; kt++) {
                uint32_t pf[4];
                pf[0] = pack_h2(sacc[2*kt][0],     sacc[2*kt][1]);
                pf[1] = pack_h2(sacc[2*kt][2],     sacc[2*kt][3]);
                pf[2] = pack_h2(sacc[2*kt + 1][0], sacc[2*kt + 1][1]);
                pf[3] = pack_h2(sacc[2*kt + 1][2], sacc[2*kt + 1][3]);
                #pragma unroll
                for (int np = 0; np < 4; np++) {
                    uint32_t bf[4];
                    int krow = kt*16 + (lane & 15);
                    int noff = np*16 + ((lane >= 16) ? 8 : 0);
                    ldsm_x4_t(bf, vsb + (krow*QSTR + noff)*2);
                    mma16816(oacc[np*2],     pf, &bf[0]);
                    mma16816(oacc[np*2 + 1], pf, &bf[2]);
                }
            }
        }
        __syncthreads();
    }

    float inv0 = 1.0f / l_i[0], inv1 = 1.0f / l_i[1];
    __half* ob = ctx + (size_t)(b*TT + qb*128 + wid*16 + (lane >> 2)) * ldg + head*DKK;
    #pragma unroll
    for (int nt = 0; nt < 8; nt++) {
        int col = nt*8 + (lane & 3)*2;
        *reinterpret_cast<__half2*>(ob + col) =
            __floats2half2_rn(oacc[nt][0]*inv0, oacc[nt][1]*inv0);
        *reinterpret_cast<__half2*>(ob + (size_t)8*ldg + col) =
            __floats2half2_rn(oacc[nt][2]*inv1, oacc[nt][3]*inv1);
    }
}

// ----------------------------------------------------------------------------
// Launch (graph-capturable: kernel launches only)
// ----------------------------------------------------------------------------
extern "C" void kernel_launch(void* const* d_in, const int* in_sizes, int n_in,
                              void* d_out, int out_size)
{
    (void)in_sizes; (void)n_in; (void)out_size;
    const float* x     = (const float*)d_in[0];
    const float* w_q   = (const float*)d_in[1];
    const float* w_k   = (const float*)d_in[2];
    const float* w_v   = (const float*)d_in[3];
    const float* w_o   = (const float*)d_in[4];
    const float* b_o   = (const float*)d_in[5];
    const float* w_fc1 = (const float*)d_in[6];
    const float* b_fc1 = (const float*)d_in[7];
    const float* w_fc2 = (const float*)d_in[8];
    const float* b_fc2 = (const float*)d_in[9];
    const float* ln1_g = (const float*)d_in[10];
    const float* ln1_b = (const float*)d_in[11];
    const float* ln2_g = (const float*)d_in[12];
    const float* ln2_b = (const float*)d_in[13];
    float* out = (float*)d_out;

    static __half *p_h16, *p_q16, *p_k16, *p_v16, *p_ctx16, *p_act16;
    static __half *p_wq16, *p_wk16, *p_wv16, *p_wo16, *p_wfc1_16, *p_wfc2_16;
    static float *p_x2;
    static bool inited = []() {
        cudaGetSymbolAddress((void**)&p_h16,     g_h16);
        cudaGetSymbolAddress((void**)&p_q16,     g_q16);
        cudaGetSymbolAddress((void**)&p_k16,     g_k16);
        cudaGetSymbolAddress((void**)&p_v16,     g_v16);
        cudaGetSymbolAddress((void**)&p_ctx16,   g_ctx16);
        cudaGetSymbolAddress((void**)&p_x2,      g_x2);
        cudaGetSymbolAddress((void**)&p_act16,   g_act16);
        cudaGetSymbolAddress((void**)&p_wq16,    g_wq16);
        cudaGetSymbolAddress((void**)&p_wk16,    g_wk16);
        cudaGetSymbolAddress((void**)&p_wv16,    g_wv16);
        cudaGetSymbolAddress((void**)&p_wo16,    g_wo16);
        cudaGetSymbolAddress((void**)&p_wfc1_16, g_wfc1_16);
        cudaGetSymbolAddress((void**)&p_wfc2_16, g_wfc2_16);
        cudaFuncSetAttribute(attn_mma_kernel,
                             cudaFuncAttributeMaxDynamicSharedMemorySize, ATTN_SMEM);
        cudaFuncSetAttribute(gemm_mma_kernel<false,false,false,true,3>,
                             cudaFuncAttributeMaxDynamicSharedMemorySize, GEMM_SMEM);
        cudaFuncSetAttribute(gemm_mma_kernel<false,true,true,false,1>,
                             cudaFuncAttributeMaxDynamicSharedMemorySize, GEMM_SMEM);
        cudaFuncSetAttribute(gemm_mma_kernel<true,false,true,true,1>,
                             cudaFuncAttributeMaxDynamicSharedMemorySize, GEMM_SMEM);
        return true;
    }();
    (void)inited;

    // All weight conversions in ONE launch
    dim3 gCvt(DD*DFF/1024, 6);
    cvt16_all_kernel<<<gCvt, 256>>>(w_q, w_k, w_v, w_o, w_fc1, w_fc2,
                                    p_wq16, p_wk16, p_wv16, p_wo16,
                                    p_wfc1_16, p_wfc2_16);

    dim3 gQKV(DD/128, MM/128, 3);   // (8, 32, 3)
    dim3 gD  (DD/128, MM/128);      // (8, 32)
    dim3 gFF (DFF/128, MM/128);     // (32, 32)
    dim3 gAtt(HH, TT/128, BZ);      // (16, 16, 2), qb reversed inside

    // h = LN1(x)  (fp16)
    ln_kernel<<<MM/8, 256>>>(x, ln1_g, ln1_b, p_h16);
    // q/k/v = h @ W_{q,k,v}  (fp16 out, one fused launch)
    gemm_mma_kernel<false,false,false,true,3><<<gQKV, 128, GEMM_SMEM>>>(
        p_h16, p_wq16, p_wk16, p_wv16, nullptr, nullptr,
        p_q16, p_k16, p_v16, DD, DD);
    // ctx = causal softmax(q k^T / 8) v  (fp16 out)
    attn_mma_kernel<<<gAtt, 256, ATTN_SMEM>>>(p_q16, p_k16, p_v16, p_ctx16);
    // x2 = x + ctx @ W_o + b_o  (fp32 out)
    gemm_mma_kernel<false,true,true,false,1><<<gD, 128, GEMM_SMEM>>>(
        p_ctx16, p_wo16, nullptr, nullptr, b_o, x,
        p_x2, nullptr, nullptr, DD, DD);
    // h = LN2(x2)  (fp16)
    ln_kernel<<<MM/8, 256>>>(p_x2, ln2_g, ln2_b, p_h16);
    // act = gelu(h @ W_fc1 + b_fc1)  (fp16 out)
    gemm_mma_kernel<true,false,true,true,1><<<gFF, 128, GEMM_SMEM>>>(
        p_h16, p_wfc1_16, nullptr, nullptr, b_fc1, nullptr,
        p_act16, nullptr, nullptr, DD, DFF);
    // out = x2 + act @ W_fc2 + b_fc2  (fp32 out)
    gemm_mma_kernel<false,true,true,false,1><<<gD, 128, GEMM_SMEM>>>(
        p_act16, p_wfc2_16, nullptr, nullptr, b_fc2, p_x2,
        out, nullptr, nullptr, DFF, DD);
}

// round 16
// speedup vs baseline: 1.0317x; 1.0317x over previous
#include <cuda_runtime.h>
#include <cuda_fp16.h>
#include <stdint.h>
#include <math.h>

#define BZ   2
#define TT   2048
#define DD   1024
#define HH   16
#define DKK  64
#define DFF  4096
#define MM   (BZ*TT)          // 4096 rows total

// ----------------------------------------------------------------------------
// Scratch (device globals — no runtime allocation allowed)
// ----------------------------------------------------------------------------
__device__ __half g_h16 [MM*DD];                // LN output (fp16 GEMM A operand)
__device__ __half g_q16 [MM*DD];
__device__ __half g_k16 [MM*DD];
__device__ __half g_v16 [MM*DD];
__device__ __half g_ctx16[MM*DD];               // attention output (fp16)
__device__ float  g_x2  [MM*DD];                // x + attn (fp32 residual stream)
__device__ __half g_act16[(size_t)MM*DFF];      // GELU(fc1) activations (fp16)
// fp16 weight copies
__device__ __half g_wq16 [DD*DD];
__device__ __half g_wk16 [DD*DD];
__device__ __half g_wv16 [DD*DD];
__device__ __half g_wo16 [DD*DD];
__device__ __half g_wfc1_16[(size_t)DD*DFF];
__device__ __half g_wfc2_16[(size_t)DFF*DD];

// ----------------------------------------------------------------------------
// Baseline-PTX tensor-core helpers (sm_80-level: valid on compute_103)
// ----------------------------------------------------------------------------
__device__ __forceinline__ uint32_t smem_u32(const void* p) {
    uint32_t a;
    asm("{ .reg .u64 t; cvta.to.shared.u64 t, %1; cvt.u32.u64 %0, t; }" : "=r"(a) : "l"(p));
    return a;
}
__device__ __forceinline__ void ldsm_x4(uint32_t r[4], uint32_t a) {
    asm volatile("ldmatrix.sync.aligned.m8n8.x4.shared.b16 {%0,%1,%2,%3}, [%4];"
        : "=r"(r[0]), "=r"(r[1]), "=r"(r[2]), "=r"(r[3]) : "r"(a));
}
__device__ __forceinline__ void ldsm_x4_t(uint32_t r[4], uint32_t a) {
    asm volatile("ldmatrix.sync.aligned.m8n8.x4.trans.shared.b16 {%0,%1,%2,%3}, [%4];"
        : "=r"(r[0]), "=r"(r[1]), "=r"(r[2]), "=r"(r[3]) : "r"(a));
}
__device__ __forceinline__ void mma16816(float c[4], const uint32_t a[4], const uint32_t b[2]) {
    asm volatile("mma.sync.aligned.m16n8k16.row.col.f32.f16.f16.f32 "
        "{%0,%1,%2,%3}, {%4,%5,%6,%7}, {%8,%9}, {%0,%1,%2,%3};"
        : "+f"(c[0]), "+f"(c[1]), "+f"(c[2]), "+f"(c[3])
        : "r"(a[0]), "r"(a[1]), "r"(a[2]), "r"(a[3]), "r"(b[0]), "r"(b[1]));
}
#define CP_ASYNC16(dst, src) \
    asm volatile("cp.async.cg.shared.global [%0], [%1], 16;" :: "r"(dst), "l"(src))
#define CP_COMMIT() asm volatile("cp.async.commit_group;")
#define CP_WAIT1()  asm volatile("cp.async.wait_group 1;")
#define CP_WAIT0()  asm volatile("cp.async.wait_group 0;")

__device__ __forceinline__ uint32_t pack_h2(float a, float b) {
    __half2 h = __floats2half2_rn(a, b);
    return *reinterpret_cast<uint32_t*>(&h);
}

// ----------------------------------------------------------------------------
// Fused fp32 -> fp16 conversion of ALL six weight tensors in one launch.
// ----------------------------------------------------------------------------
__global__ void __launch_bounds__(256) cvt16_all_kernel(
        const float* __restrict__ s0, const float* __restrict__ s1,
        const float* __restrict__ s2, const float* __restrict__ s3,
        const float* __restrict__ s4, const float* __restrict__ s5,
        __half* __restrict__ d0, __half* __restrict__ d1,
        __half* __restrict__ d2, __half* __restrict__ d3,
        __half* __restrict__ d4, __half* __restrict__ d5)
{
    const float* s; __half* d; int n;
    switch (blockIdx.y) {
        case 0:  s = s0; d = d0; n = DD*DD;  break;
        case 1:  s = s1; d = d1; n = DD*DD;  break;
        case 2:  s = s2; d = d2; n = DD*DD;  break;
        case 3:  s = s3; d = d3; n = DD*DD;  break;
        case 4:  s = s4; d = d4; n = DD*DFF; break;
        default: s = s5; d = d5; n = DFF*DD; break;
    }
    int i = (blockIdx.x * 256 + threadIdx.x) * 4;
    if (i < n) {
        float4 v = *reinterpret_cast<const float4*>(s + i);
        __align__(8) __half2 hv[2] = { __floats2half2_rn(v.x, v.y),
                                       __floats2half2_rn(v.z, v.w) };
        *reinterpret_cast<uint2*>(d + i) = *reinterpret_cast<uint2*>(hv);
    }
}

// ----------------------------------------------------------------------------
// LayerNorm (torch semantics: unbiased std ddof=1, eps added to std). fp16 out.
// Warp-per-row, 8 rows per 256-thread block, NO __syncthreads.
// ----------------------------------------------------------------------------
__global__ void __launch_bounds__(256) ln_kernel(const float* __restrict__ x,
        const float* __restrict__ g, const float* __restrict__ b,
        __half* __restrict__ out)
{
    int row  = blockIdx.x * 8 + (threadIdx.x >> 5);
    int lane = threadIdx.x & 31;
    const float* xr = x + (size_t)row * DD;

    float4 xv[8];
    float s1 = 0.f, s2 = 0.f;
    #pragma unroll
    for (int i = 0; i < 8; i++) {
        xv[i] = *reinterpret_cast<const float4*>(xr + i*128 + lane*4);
        s1 += xv[i].x + xv[i].y + xv[i].z + xv[i].w;
        s2 += xv[i].x*xv[i].x + xv[i].y*xv[i].y + xv[i].z*xv[i].z + xv[i].w*xv[i].w;
    }
    #pragma unroll
    for (int o = 16; o > 0; o >>= 1) {
        s1 += __shfl_xor_sync(0xffffffffu, s1, o);
        s2 += __shfl_xor_sync(0xffffffffu, s2, o);
    }
    float mean = s1 * (1.0f / DD);
    float var  = (s2 - s1 * mean) * (1.0f / (DD - 1));   // unbiased (ddof=1)
    var = fmaxf(var, 0.f);
    float rstd = 1.0f / (sqrtf(var) + 1e-6f);            // eps added to std

    __half* orow = out + (size_t)row * DD;
    #pragma unroll
    for (int i = 0; i < 8; i++) {
        float4 gv = *reinterpret_cast<const float4*>(g + i*128 + lane*4);
        float4 bv = *reinterpret_cast<const float4*>(b + i*128 + lane*4);
        float o0 = (xv[i].x - mean) * gv.x * rstd + bv.x;
        float o1 = (xv[i].y - mean) * gv.y * rstd + bv.y;
        float o2 = (xv[i].z - mean) * gv.z * rstd + bv.z;
        float o3 = (xv[i].w - mean) * gv.w * rstd + bv.w;
        __align__(8) __half2 hv[2] = { __floats2half2_rn(o0, o1),
                                       __floats2half2_rn(o2, o3) };
        *reinterpret_cast<uint2*>(orow + i*128 + lane*4) = *reinterpret_cast<uint2*>(hv);
    }
}

// ----------------------------------------------------------------------------
// mma.sync fp16 GEMM: C = A @ B (+bias/GELU/resid). CTA 128x128, BK=32,
// 4 warps x 64x64 warp tiles, 3-stage cp.async pipeline, one __syncthreads per
// K-step. EXACT R12/R14 configuration (proven fastest — do not touch).
// ----------------------------------------------------------------------------
#define ASTR 40
#define BSTR 136
#define A_STG (128*ASTR)              // halves per A stage
#define B_STG (32*BSTR)               // halves per B stage
#define GEMM_SMEM ((3*A_STG + 3*B_STG)*2)   // 56832 bytes

template<bool GELU, bool RESID, bool BIAS, bool OUT16, int NB>
__global__ void __launch_bounds__(128) gemm_mma_kernel(
        const __half* __restrict__ A,
        const __half* __restrict__ B0, const __half* __restrict__ B1,
        const __half* __restrict__ B2,
        const float* __restrict__ bias, const float* __restrict__ resid,
        void* C0, void* C1, void* C2, int Kdim, int Ndim)
{
    extern __shared__ __align__(16) char gsm[];
    __half* As = reinterpret_cast<__half*>(gsm);
    __half* Bs = As + 3*A_STG;

    int tid = threadIdx.x;
    int wid = tid >> 5, lane = tid & 31;
    int wm = wid & 1, wn = wid >> 1;    // 2x2 warps, each 64x64

    const __half* B = B0;
    void* Cv = C0;
    if (NB == 3) {
        if (blockIdx.z == 1)      { B = B1; Cv = C1; }
        else if (blockIdx.z == 2) { B = B2; Cv = C2; }
    }

    int brow = blockIdx.y * 128;
    int bcol = blockIdx.x * 128;
    const __half* Ag = A + (size_t)brow * Kdim;
    const __half* Bg = B + bcol;

    float acc[4][8][4];
    #pragma unroll
    for (int mt = 0; mt < 4; mt++)
        #pragma unroll
        for (int nt = 0; nt < 8; nt++)
            #pragma unroll
            for (int e = 0; e < 4; e++) acc[mt][nt][e] = 0.f;

    auto load_tiles = [&](int stg, int k0) {
        uint32_t ab = smem_u32(As + stg * A_STG);
        #pragma unroll
        for (int u = 0; u < 4; u++) {
            int c = tid + u * 128;
            int row = c >> 2, seg = c & 3;
            CP_ASYNC16(ab + (row*ASTR + seg*8)*2,
                       Ag + (size_t)row * Kdim + k0 + seg*8);
        }
        uint32_t bb = smem_u32(Bs + stg * B_STG);
        #pragma unroll
        for (int u = 0; u < 4; u++) {
            int c = tid + u * 128;
            int row = c >> 4, seg = c & 15;
            CP_ASYNC16(bb + (row*BSTR + seg*8)*2,
                       Bg + (size_t)(k0 + row) * Ndim + seg*8);
        }
    };

    int nk = Kdim >> 5;
    load_tiles(0, 0);  CP_COMMIT();
    load_tiles(1, 32); CP_COMMIT();    // nk >= 2 always (K >= 64)

    int lrow = lane & 15, lcol = lane >> 4;
    int stg = 0;

    for (int i = 0; i < nk; i++) {
        if (i == nk - 1) { CP_WAIT0(); } else { CP_WAIT1(); }
        __syncthreads();     // stage i visible; compute i-1 done everywhere

        uint32_t ab = smem_u32(As + stg * A_STG);
        uint32_t bb = smem_u32(Bs + stg * B_STG);
        #pragma unroll
        for (int ks = 0; ks < 2; ks++) {
            uint32_t af[4][4];
            #pragma unroll
            for (int mt = 0; mt < 4; mt++)
                ldsm_x4(af[mt], ab + ((wm*64 + mt*16 + lrow)*ASTR + ks*16 + lcol*8)*2);
            uint32_t bf[4][4];
            #pragma unroll
            for (int t = 0; t < 4; t++)
                ldsm_x4_t(bf[t], bb + ((ks*16 + lrow)*BSTR + wn*64 + t*16 + lcol*8)*2);
            #pragma unroll
            for (int mt = 0; mt < 4; mt++)
                #pragma unroll
                for (int nt = 0; nt < 8; nt++)
                    mma16816(acc[mt][nt], af[mt], &bf[nt >> 1][(nt & 1) * 2]);
        }

        if (i + 2 < nk) {
            int ns = stg + 2; if (ns >= 3) ns -= 3;
            load_tiles(ns, (i + 2) << 5);
            CP_COMMIT();
        }
        if (++stg == 3) stg = 0;
    }

    int r0 = brow + wm*64 + (lane >> 2);
    int c0 = bcol + wn*64 + (lane & 3) * 2;
    #pragma unroll
    for (int mt = 0; mt < 4; mt++) {
        #pragma unroll
        for (int hh = 0; hh < 2; hh++) {
            int r = r0 + mt*16 + hh*8;
            #pragma unroll
            for (int nt = 0; nt < 8; nt++) {
                int c = c0 + nt*8;
                float v0 = acc[mt][nt][hh*2 + 0];
                float v1 = acc[mt][nt][hh*2 + 1];
                if (BIAS) { v0 += bias[c]; v1 += bias[c + 1]; }
                if (GELU) {
                    v0 = 0.5f * v0 * (1.0f + erff(v0 * 0.70710678118f));
                    v1 = 0.5f * v1 * (1.0f + erff(v1 * 0.70710678118f));
                }
                if (RESID) {
                    v0 += resid[(size_t)r * Ndim + c];
                    v1 += resid[(size_t)r * Ndim + c + 1];
                }
                if (OUT16) {
                    __half2 hv = __floats2half2_rn(v0, v1);
                    *reinterpret_cast<__half2*>((__half*)Cv + (size_t)r * Ndim + c) = hv;
                } else {
                    *reinterpret_cast<float2*>((float*)Cv + (size_t)r * Ndim + c) =
                        make_float2(v0, v1);
                }
            }
        }
    }
}

// ----------------------------------------------------------------------------
// FA2-style causal attention via mma.sync, 128-query blocks, 8 warps.
// R16: K/V ring = 3 buffers -> ONE __syncthreads per key tile (pipeline
// theorem: load kb+2 overwrites slot (kb-1)%3 whose compute finished before
// this barrier; wait_group 1 guarantees tile kb is resident).
// Grid (HH, TT/128, BZ) with REVERSED qb so heavy causal blocks launch first.
// ----------------------------------------------------------------------------
#define QSTR 72
#define KV_STG (64*QSTR)                             // halves per K or V buffer
#define ATTN_SMEM ((128*QSTR + 6*KV_STG)*2)          // Q + 3x(K,V) = 73728 B

__global__ void __launch_bounds__(256, 2) attn_mma_kernel(
        const __half* __restrict__ q, const __half* __restrict__ k,
        const __half* __restrict__ v, __half* __restrict__ ctx)
{
    extern __shared__ __align__(16) char dsm[];
    __half* Qs = reinterpret_cast<__half*>(dsm);
    __half* Kb[3] = { Qs + 128*QSTR,            Qs + 128*QSTR + 2*KV_STG,
                      Qs + 128*QSTR + 4*KV_STG };
    __half* Vb[3] = { Qs + 128*QSTR + KV_STG,   Qs + 128*QSTR + 3*KV_STG,
                      Qs + 128*QSTR + 5*KV_STG };

    int head = blockIdx.x;
    int qb   = gridDim.y - 1 - blockIdx.y;   // heavy blocks (large qb) first
    int b    = blockIdx.z;
    int tid = threadIdx.x, wid = tid >> 5, lane = tid & 31;
    const int ldg = HH * DKK;   // 1024

    const __half* qbase = q + (size_t)(b*TT + qb*128) * ldg + head*DKK;
    const __half* kbase = k + (size_t)(b*TT) * ldg + head*DKK;
    const __half* vbase = v + (size_t)(b*TT) * ldg + head*DKK;

    #pragma unroll
    for (int u = 0; u < 4; u++) {
        int c = tid + u * 256;
        int row = c >> 3, seg = c & 7;
        *reinterpret_cast<uint4*>(&Qs[row*QSTR + seg*8]) =
            *reinterpret_cast<const uint4*>(qbase + (size_t)row * ldg + seg*8);
    }

    auto load_kv = [&](int buf, int kb) {
        uint32_t kB = smem_u32(Kb[buf]);
        uint32_t vB = smem_u32(Vb[buf]);
        #pragma unroll
        for (int u = 0; u < 2; u++) {
            int c = tid + u * 256;
            int row = c >> 3, seg = c & 7;
            const __half* ks = kbase + (size_t)(kb*64 + row) * ldg + seg*8;
            const __half* vs = vbase + (size_t)(kb*64 + row) * ldg + seg*8;
            CP_ASYNC16(kB + (row*QSTR + seg*8)*2, ks);
            CP_ASYNC16(vB + (row*QSTR + seg*8)*2, vs);
        }
    };

    int nkb = 2*qb + 2;            // key tiles 0 .. 2qb+1 (nkb >= 2)
    load_kv(0, 0);
    CP_COMMIT();
    load_kv(1, 1);
    CP_COMMIT();
    __syncthreads();               // Q visible (covers Q store -> qf loads)

    uint32_t qsb = smem_u32(Qs);
    int lrow = lane & 15, lcol = lane >> 4;
    uint32_t qf[4][4];
    #pragma unroll
    for (int kt = 0; kt < 4; kt++)
        ldsm_x4(qf[kt], qsb + ((wid*16 + lrow)*QSTR + kt*16 + lcol*8)*2);

    float m_i[2] = {-1e30f, -1e30f}, l_i[2] = {0.f, 0.f};
    float oacc[8][4];
    #pragma unroll
    for (int nt = 0; nt < 8; nt++)
        #pragma unroll
        for (int e = 0; e < 4; e++) oacc[nt][e] = 0.f;

    int wr_lo = qb*128 + wid*16;
    int qrow0 = wr_lo + (lane >> 2);
    int buf = 0;

    for (int kb = 0; kb < nkb; kb++) {
        // tile kb resident <=> at most (exists kb+1 ? 1 : 0) newer groups pending
        if (kb + 1 < nkb) { CP_WAIT1(); } else { CP_WAIT0(); }
        __syncthreads();   // ONE barrier: tile kb visible; compute kb-1 done

        // Prefetch tile kb+2 into slot (kb+2)%3 == (kb-1)%3 (safe: compute
        // kb-1 finished before the barrier above).
        if (kb + 2 < nkb) {
            int nb = buf + 2; if (nb >= 3) nb -= 3;
            load_kv(nb, kb + 2);
            CP_COMMIT();
        }

        if (kb*64 <= wr_lo + 15) {
            uint32_t ksb = smem_u32(Kb[buf]);
            uint32_t vsb = smem_u32(Vb[buf]);
            bool need_mask = (kb*64 + 63 > wr_lo);

            float sacc[8][4];
            #pragma unroll
            for (int nt = 0; nt < 8; nt++)
                #pragma unroll
                for (int e = 0; e < 4; e++) sacc[nt][e] = 0.f;

            #pragma unroll
            for (int kt = 0; kt < 4; kt++) {
                #pragma unroll
                for (int np = 0; np < 4; np++) {
                    uint32_t bf[4];
                    int nrow = np*16 + (lane & 7) + ((lane >= 16) ? 8 : 0);
                    int koff = kt*16 + ((lane & 8) ? 8 : 0);
                    ldsm_x4(bf, ksb + (nrow*QSTR + koff)*2);
                    mma16816(sacc[np*2],     qf[kt], &bf[0]);
                    mma16816(sacc[np*2 + 1], qf[kt], &bf[2]);
                }
            }

            if (need_mask) {
                #pragma unroll
                for (int nt = 0; nt < 8; nt++) {
                    int kcol = kb*64 + nt*8 + (lane & 3)*2;
                    #pragma unroll
                    for (int e = 0; e < 4; e++) {
                        int r = qrow0 + ((e >= 2) ? 8 : 0);
                        int c = kcol + (e & 1);
                        sacc[nt][e] = (c <= r) ? sacc[nt][e] * 0.125f : -1e30f;
                    }
                }
            } else {
                #pragma unroll
                for (int nt = 0; nt < 8; nt++)
                    #pragma unroll
                    for (int e = 0; e < 4; e++) sacc[nt][e] *= 0.125f;
            }

            float mx[2] = {-1e30f, -1e30f};
            #pragma unroll
            for (int nt = 0; nt < 8; nt++) {
                mx[0] = fmaxf(mx[0], fmaxf(sacc[nt][0], sacc[nt][1]));
                mx[1] = fmaxf(mx[1], fmaxf(sacc[nt][2], sacc[nt][3]));
            }
            #pragma unroll
            for (int hh = 0; hh < 2; hh++) {
                mx[hh] = fmaxf(mx[hh], __shfl_xor_sync(0xffffffffu, mx[hh], 1));
                mx[hh] = fmaxf(mx[hh], __shfl_xor_sync(0xffffffffu, mx[hh], 2));
            }
            float mnew[2] = { fmaxf(m_i[0], mx[0]), fmaxf(m_i[1], mx[1]) };
            float corr[2] = { __expf(m_i[0] - mnew[0]), __expf(m_i[1] - mnew[1]) };
            float ps[2] = {0.f, 0.f};
            #pragma unroll
            for (int nt = 0; nt < 8; nt++) {
                #pragma unroll
                for (int e = 0; e < 4; e++) {
                    float p = __expf(sacc[nt][e] - mnew[(e >= 2) ? 1 : 0]);
                    sacc[nt][e] = p;
                    ps[(e >= 2) ? 1 : 0] += p;
                }
            }
            #pragma unroll
            for (int hh = 0; hh < 2; hh++) {
                ps[hh] += __shfl_xor_sync(0xffffffffu, ps[hh], 1);
                ps[hh] += __shfl_xor_sync(0xffffffffu, ps[hh], 2);
                l_i[hh] = l_i[hh] * corr[hh] + ps[hh];
                m_i[hh] = mnew[hh];
            }
            #pragma unroll
            for (int nt = 0; nt < 8; nt++) {
                oacc[nt][0] *= corr[0]; oacc[nt][1] *= corr[0];
                oacc[nt][2] *= corr[1]; oacc[nt][3] *= corr[1];
            }

            #pragma unroll
            for (int kt = 0; kt < 4; kt++) {
                uint32_t pf[4];
                pf[0] = pack_h2(sacc[2*kt][0],     sacc[2*kt][1]);
                pf[1] = pack_h2(sacc[2*kt][2],     sacc[2*kt][3]);
                pf[2] = pack_h2(sacc[2*kt + 1][0], sacc[2*kt + 1][1]);
                pf[3] = pack_h2(sacc[2*kt + 1][2], sacc[2*kt + 1][3]);
                #pragma unroll
                for (int np = 0; np < 4; np++) {
                    uint32_t bf[4];
                    int krow = kt*16 + (lane & 15);
                    int noff = np*16 + ((lane >= 16) ? 8 : 0);
                    ldsm_x4_t(bf, vsb + (krow*QSTR + noff)*2);
                    mma16816(oacc[np*2],     pf, &bf[0]);
                    mma16816(oacc[np*2 + 1], pf, &bf[2]);
                }
            }
        }
        if (++buf == 3) buf = 0;
    }

    float inv0 = 1.0f / l_i[0], inv1 = 1.0f / l_i[1];
    __half* ob = ctx + (size_t)(b*TT + qb*128 + wid*16 + (lane >> 2)) * ldg + head*DKK;
    #pragma unroll
    for (int nt = 0; nt < 8; nt++) {
        int col = nt*8 + (lane & 3)*2;
        *reinterpret_cast<__half2*>(ob + col) =
            __floats2half2_rn(oacc[nt][0]*inv0, oacc[nt][1]*inv0);
        *reinterpret_cast<__half2*>(ob + (size_t)8*ldg + col) =
            __floats2half2_rn(oacc[nt][2]*inv1, oacc[nt][3]*inv1);
    }
}

// ----------------------------------------------------------------------------
// Launch (graph-capturable: kernel launches only)
// ----------------------------------------------------------------------------
extern "C" void kernel_launch(void* const* d_in, const int* in_sizes, int n_in,
                              void* d_out, int out_size)
{
    (void)in_sizes; (void)n_in; (void)out_size;
    const float* x     = (const float*)d_in[0];
    const float* w_q   = (const float*)d_in[1];
    const float* w_k   = (const float*)d_in[2];
    const float* w_v   = (const float*)d_in[3];
    const float* w_o   = (const float*)d_in[4];
    const float* b_o   = (const float*)d_in[5];
    const float* w_fc1 = (const float*)d_in[6];
    const float* b_fc1 = (const float*)d_in[7];
    const float* w_fc2 = (const float*)d_in[8];
    const float* b_fc2 = (const float*)d_in[9];
    const float* ln1_g = (const float*)d_in[10];
    const float* ln1_b = (const float*)d_in[11];
    const float* ln2_g = (const float*)d_in[12];
    const float* ln2_b = (const float*)d_in[13];
    float* out = (float*)d_out;

    static __half *p_h16, *p_q16, *p_k16, *p_v16, *p_ctx16, *p_act16;
    static __half *p_wq16, *p_wk16, *p_wv16, *p_wo16, *p_wfc1_16, *p_wfc2_16;
    static float *p_x2;
    static bool inited = []() {
        cudaGetSymbolAddress((void**)&p_h16,     g_h16);
        cudaGetSymbolAddress((void**)&p_q16,     g_q16);
        cudaGetSymbolAddress((void**)&p_k16,     g_k16);
        cudaGetSymbolAddress((void**)&p_v16,     g_v16);
        cudaGetSymbolAddress((void**)&p_ctx16,   g_ctx16);
        cudaGetSymbolAddress((void**)&p_x2,      g_x2);
        cudaGetSymbolAddress((void**)&p_act16,   g_act16);
        cudaGetSymbolAddress((void**)&p_wq16,    g_wq16);
        cudaGetSymbolAddress((void**)&p_wk16,    g_wk16);
        cudaGetSymbolAddress((void**)&p_wv16,    g_wv16);
        cudaGetSymbolAddress((void**)&p_wo16,    g_wo16);
        cudaGetSymbolAddress((void**)&p_wfc1_16, g_wfc1_16);
        cudaGetSymbolAddress((void**)&p_wfc2_16, g_wfc2_16);
        cudaFuncSetAttribute(attn_mma_kernel,
                             cudaFuncAttributeMaxDynamicSharedMemorySize, ATTN_SMEM);
        cudaFuncSetAttribute(gemm_mma_kernel<false,false,false,true,3>,
                             cudaFuncAttributeMaxDynamicSharedMemorySize, GEMM_SMEM);
        cudaFuncSetAttribute(gemm_mma_kernel<false,true,true,false,1>,
                             cudaFuncAttributeMaxDynamicSharedMemorySize, GEMM_SMEM);
        cudaFuncSetAttribute(gemm_mma_kernel<true,false,true,true,1>,
                             cudaFuncAttributeMaxDynamicSharedMemorySize, GEMM_SMEM);
        return true;
    }();
    (void)inited;

    // All weight conversions in ONE launch
    dim3 gCvt(DD*DFF/1024, 6);
    cvt16_all_kernel<<<gCvt, 256>>>(w_q, w_k, w_v, w_o, w_fc1, w_fc2,
                                    p_wq16, p_wk16, p_wv16, p_wo16,
                                    p_wfc1_16, p_wfc2_16);

    dim3 gQKV(DD/128, MM/128, 3);   // (8, 32, 3)
    dim3 gD  (DD/128, MM/128);      // (8, 32)
    dim3 gFF (DFF/128, MM/128);     // (32, 32)
    dim3 gAtt(HH, TT/128, BZ);      // (16, 16, 2), qb reversed inside

    // h = LN1(x)  (fp16)
    ln_kernel<<<MM/8, 256>>>(x, ln1_g, ln1_b, p_h16);
    // q/k/v = h @ W_{q,k,v}  (fp16 out, one fused launch)
    gemm_mma_kernel<false,false,false,true,3><<<gQKV, 128, GEMM_SMEM>>>(
        p_h16, p_wq16, p_wk16, p_wv16, nullptr, nullptr,
        p_q16, p_k16, p_v16, DD, DD);
    // ctx = causal softmax(q k^T / 8) v  (fp16 out)
    attn_mma_kernel<<<gAtt, 256, ATTN_SMEM>>>(p_q16, p_k16, p_v16, p_ctx16);
    // x2 = x + ctx @ W_o + b_o  (fp32 out)
    gemm_mma_kernel<false,true,true,false,1><<<gD, 128, GEMM_SMEM>>>(
        p_ctx16, p_wo16, nullptr, nullptr, b_o, x,
        p_x2, nullptr, nullptr, DD, DD);
    // h = LN2(x2)  (fp16)
    ln_kernel<<<MM/8, 256>>>(p_x2, ln2_g, ln2_b, p_h16);
    // act = gelu(h @ W_fc1 + b_fc1)  (fp16 out)
    gemm_mma_kernel<true,false,true,true,1><<<gFF, 128, GEMM_SMEM>>>(
        p_h16, p_wfc1_16, nullptr, nullptr, b_fc1, nullptr,
        p_act16, nullptr, nullptr, DD, DFF);
    // out = x2 + act @ W_fc2 + b_fc2  (fp32 out)
    gemm_mma_kernel<false,true,true,false,1><<<gD, 128, GEMM_SMEM>>>(
        p_act16, p_wfc2_16, nullptr, nullptr, b_fc2, p_x2,
        out, nullptr, nullptr, DFF, DD);
}